// round 3
// baseline (speedup 1.0000x reference)
#include <cuda_runtime.h>

#define N_NODES 100000
#define IN_DIM 128
#define HIDDEN 64
#define TN 128   // nodes per block tile in GEMM kernels

// Scratch (allocation-guard-safe: __device__ globals)
__device__ float g_weights[N_NODES];
__device__ float g_readout[(size_t)N_NODES * IN_DIM];

// ---------------------------------------------------------------------------
// Packed f32x2 helpers (sm_103a)
// ---------------------------------------------------------------------------
__device__ __forceinline__ unsigned long long pack2(float a, float b) {
    unsigned long long r;
    asm("mov.b64 %0, {%1, %2};" : "=l"(r) : "f"(a), "f"(b));
    return r;
}
__device__ __forceinline__ void fma2(unsigned long long& d,
                                     unsigned long long a,
                                     unsigned long long b) {
    asm("fma.rn.f32x2 %0, %1, %2, %0;" : "+l"(d) : "l"(a), "l"(b));
}
__device__ __forceinline__ void unpack2(unsigned long long v, float& lo, float& hi) {
    asm("mov.b64 {%0, %1}, %2;" : "=f"(lo), "=f"(hi) : "l"(v));
}
__device__ __forceinline__ float tanh_fast(float x) {
    float y;
    asm("tanh.approx.f32 %0, %1;" : "=f"(y) : "f"(x));
    return y;
}

// ---------------------------------------------------------------------------
// Kernel 1: gate  weights[n] = sigmoid(tanh(x@W_sim+b_sim)@w_vec+b_vec)
// Tile: 128 nodes/block, 256 threads. Thread = 4 nodes (tx+32i) x 8 hidden (ty*8+j).
// ---------------------------------------------------------------------------
__global__ void __launch_bounds__(256)
gate_kernel(const float* __restrict__ x,
            const float* __restrict__ W_sim,
            const float* __restrict__ b_sim,
            const float* __restrict__ w_vec,
            const float* __restrict__ b_vec,
            int N) {
    __shared__ __align__(16) float Ws[IN_DIM * HIDDEN];  // 32 KB
    __shared__ __align__(16) float bs[HIDDEN];
    __shared__ float wv[HIDDEN];
    __shared__ float part[8][TN];

    for (int i = threadIdx.x; i < IN_DIM * HIDDEN; i += 256) Ws[i] = W_sim[i];
    if (threadIdx.x < HIDDEN) { bs[threadIdx.x] = b_sim[threadIdx.x]; wv[threadIdx.x] = w_vec[threadIdx.x]; }
    __syncthreads();

    const int tx = threadIdx.x & 31;
    const int ty = threadIdx.x >> 5;
    const int h0 = ty * 8;
    const int base = blockIdx.x * TN;

    int   nn[4];
    bool  ok[4];
#pragma unroll
    for (int i = 0; i < 4; i++) { nn[i] = base + tx + 32 * i; ok[i] = nn[i] < N; }

    unsigned long long acc[4][4];
    {
        ulonglong2 b01 = *reinterpret_cast<const ulonglong2*>(&bs[h0]);
        ulonglong2 b23 = *reinterpret_cast<const ulonglong2*>(&bs[h0 + 4]);
#pragma unroll
        for (int i = 0; i < 4; i++) {
            acc[i][0] = b01.x; acc[i][1] = b01.y; acc[i][2] = b23.x; acc[i][3] = b23.y;
        }
    }

    const float4* x4 = reinterpret_cast<const float4*>(x);
#pragma unroll 4
    for (int k4 = 0; k4 < IN_DIM / 4; k4++) {
        float4 a[4];
#pragma unroll
        for (int i = 0; i < 4; i++)
            a[i] = ok[i] ? x4[(size_t)nn[i] * (IN_DIM / 4) + k4]
                         : make_float4(0.f, 0.f, 0.f, 0.f);
#pragma unroll
        for (int kk = 0; kk < 4; kk++) {
            const float* wr = Ws + (k4 * 4 + kk) * HIDDEN + h0;
            ulonglong2 w01 = *reinterpret_cast<const ulonglong2*>(wr);
            ulonglong2 w23 = *reinterpret_cast<const ulonglong2*>(wr + 4);
#pragma unroll
            for (int i = 0; i < 4; i++) {
                float xv = (kk == 0) ? a[i].x : (kk == 1) ? a[i].y : (kk == 2) ? a[i].z : a[i].w;
                unsigned long long xp = pack2(xv, xv);
                fma2(acc[i][0], xp, w01.x);
                fma2(acc[i][1], xp, w01.y);
                fma2(acc[i][2], xp, w23.x);
                fma2(acc[i][3], xp, w23.y);
            }
        }
    }

    // tanh + dot with w_vec over this thread's 8 hidden dims
    float p[4] = {0.f, 0.f, 0.f, 0.f};
#pragma unroll
    for (int j = 0; j < 4; j++) {
        float wlo = wv[h0 + 2 * j], whi = wv[h0 + 2 * j + 1];
#pragma unroll
        for (int i = 0; i < 4; i++) {
            float t0, t1;
            unpack2(acc[i][j], t0, t1);
            p[i] = fmaf(tanh_fast(t0), wlo, p[i]);
            p[i] = fmaf(tanh_fast(t1), whi, p[i]);
        }
    }
#pragma unroll
    for (int i = 0; i < 4; i++) part[ty][tx + 32 * i] = p[i];
    __syncthreads();

    if (threadIdx.x < TN) {
        int n = base + threadIdx.x;
        if (n < N) {
            float s = b_vec[0];
#pragma unroll
            for (int r = 0; r < 8; r++) s += part[r][threadIdx.x];
            g_weights[n] = 1.0f / (1.0f + expf(-s));
        }
    }
}

// ---------------------------------------------------------------------------
// Kernel 2: zero the readout accumulator
// ---------------------------------------------------------------------------
__global__ void zero_kernel(size_t n4) {
    size_t i = (size_t)blockIdx.x * blockDim.x + threadIdx.x;
    if (i < n4) reinterpret_cast<float4*>(g_readout)[i] = make_float4(0.f, 0.f, 0.f, 0.f);
}

// ---------------------------------------------------------------------------
// Kernel 3: scatter  readout[row] += x[col] * weights[col]   (warp per edge)
// ---------------------------------------------------------------------------
__device__ __forceinline__ void red_add_v4(float* addr, float4 v) {
    asm volatile("red.global.add.v4.f32 [%0], {%1,%2,%3,%4};"
                 :: "l"(addr), "f"(v.x), "f"(v.y), "f"(v.z), "f"(v.w)
                 : "memory");
}

__global__ void scatter_kernel(const float* __restrict__ x,
                               const int* __restrict__ ei,   // [2, E] int32
                               long long E) {
    long long w = (long long)blockIdx.x * (blockDim.x >> 5) + (threadIdx.x >> 5);
    if (w >= E) return;
    int lane = threadIdx.x & 31;
    int row = ei[w];        // destination
    int col = ei[E + w];    // source
    float g = g_weights[col];
    float4 v = reinterpret_cast<const float4*>(x)[(size_t)col * (IN_DIM / 4) + lane];
    v.x *= g; v.y *= g; v.z *= g; v.w *= g;
    float* dst = g_readout + (size_t)row * IN_DIM + lane * 4;
    red_add_v4(dst, v);
}

// ---------------------------------------------------------------------------
// Kernel 4: out = x + relu(readout@W1+b1)@W2 + b2
// Tile: 128 nodes/block, 256 threads.
// Stage1: thread = 4 nodes x 8 hidden.  Stage2: thread = 4 nodes x 16 out.
// h exchanged via transposed smem tile [HIDDEN][TN+4].
// ---------------------------------------------------------------------------
#define HT_PAD (TN + 4)

__global__ void __launch_bounds__(256)
mlp_kernel(const float* __restrict__ x,
           const float* __restrict__ W1,
           const float* __restrict__ b1,
           const float* __restrict__ W2,
           const float* __restrict__ b2,
           float* __restrict__ out, int N) {
    extern __shared__ __align__(16) float smem[];
    float* W1s = smem;                         // 8192
    float* W2s = smem + 8192;                  // 8192
    float* hT  = smem + 16384;                 // HIDDEN * HT_PAD = 8448
    float* b1s = smem + 16384 + HIDDEN * HT_PAD;       // 64
    float* b2s = b1s + HIDDEN;                          // 128

    for (int i = threadIdx.x; i < 8192; i += 256) { W1s[i] = W1[i]; W2s[i] = W2[i]; }
    if (threadIdx.x < HIDDEN) b1s[threadIdx.x] = b1[threadIdx.x];
    if (threadIdx.x < IN_DIM) b2s[threadIdx.x] = b2[threadIdx.x];
    __syncthreads();

    const int tx = threadIdx.x & 31;
    const int ty = threadIdx.x >> 5;
    const int base = blockIdx.x * TN;

    int  nn[4];
    bool ok[4];
#pragma unroll
    for (int i = 0; i < 4; i++) { nn[i] = base + tx + 32 * i; ok[i] = nn[i] < N; }

    // ---- stage 1: h = relu(readout @ W1 + b1) ----
    {
        const int h0 = ty * 8;
        unsigned long long acc[4][4];
        ulonglong2 b01 = *reinterpret_cast<const ulonglong2*>(&b1s[h0]);
        ulonglong2 b23 = *reinterpret_cast<const ulonglong2*>(&b1s[h0 + 4]);
#pragma unroll
        for (int i = 0; i < 4; i++) {
            acc[i][0] = b01.x; acc[i][1] = b01.y; acc[i][2] = b23.x; acc[i][3] = b23.y;
        }

        const float4* r4 = reinterpret_cast<const float4*>(g_readout);
#pragma unroll 4
        for (int k4 = 0; k4 < IN_DIM / 4; k4++) {
            float4 a[4];
#pragma unroll
            for (int i = 0; i < 4; i++)
                a[i] = ok[i] ? r4[(size_t)nn[i] * (IN_DIM / 4) + k4]
                             : make_float4(0.f, 0.f, 0.f, 0.f);
#pragma unroll
            for (int kk = 0; kk < 4; kk++) {
                const float* wr = W1s + (k4 * 4 + kk) * HIDDEN + h0;
                ulonglong2 w01 = *reinterpret_cast<const ulonglong2*>(wr);
                ulonglong2 w23 = *reinterpret_cast<const ulonglong2*>(wr + 4);
#pragma unroll
                for (int i = 0; i < 4; i++) {
                    float xv = (kk == 0) ? a[i].x : (kk == 1) ? a[i].y : (kk == 2) ? a[i].z : a[i].w;
                    unsigned long long xp = pack2(xv, xv);
                    fma2(acc[i][0], xp, w01.x);
                    fma2(acc[i][1], xp, w01.y);
                    fma2(acc[i][2], xp, w23.x);
                    fma2(acc[i][3], xp, w23.y);
                }
            }
        }

        // relu + transpose into hT[h][node]
#pragma unroll
        for (int j = 0; j < 4; j++) {
#pragma unroll
            for (int i = 0; i < 4; i++) {
                float t0, t1;
                unpack2(acc[i][j], t0, t1);
                hT[(h0 + 2 * j)     * HT_PAD + tx + 32 * i] = fmaxf(t0, 0.f);
                hT[(h0 + 2 * j + 1) * HT_PAD + tx + 32 * i] = fmaxf(t1, 0.f);
            }
        }
    }
    __syncthreads();

    // ---- stage 2: out = x + h @ W2 + b2 ----
    {
        const int d0 = ty * 16;
        unsigned long long acc[4][8];
        {
            const ulonglong2* bp = reinterpret_cast<const ulonglong2*>(&b2s[d0]);
#pragma unroll
            for (int q = 0; q < 4; q++) {
                ulonglong2 b = bp[q];
#pragma unroll
                for (int i = 0; i < 4; i++) { acc[i][2 * q] = b.x; acc[i][2 * q + 1] = b.y; }
            }
        }

#pragma unroll 4
        for (int k = 0; k < HIDDEN; k++) {
            float hv[4];
#pragma unroll
            for (int i = 0; i < 4; i++) hv[i] = hT[k * HT_PAD + tx + 32 * i];
            const ulonglong2* wp = reinterpret_cast<const ulonglong2*>(W2s + k * IN_DIM + d0);
            ulonglong2 w0 = wp[0], w1 = wp[1], w2 = wp[2], w3 = wp[3];
#pragma unroll
            for (int i = 0; i < 4; i++) {
                unsigned long long xp = pack2(hv[i], hv[i]);
                fma2(acc[i][0], xp, w0.x); fma2(acc[i][1], xp, w0.y);
                fma2(acc[i][2], xp, w1.x); fma2(acc[i][3], xp, w1.y);
                fma2(acc[i][4], xp, w2.x); fma2(acc[i][5], xp, w2.y);
                fma2(acc[i][6], xp, w3.x); fma2(acc[i][7], xp, w3.y);
            }
        }

        // epilogue: + x, store
        const float4* x4 = reinterpret_cast<const float4*>(x);
        float4* o4 = reinterpret_cast<float4*>(out);
#pragma unroll
        for (int i = 0; i < 4; i++) {
            if (!ok[i]) continue;
#pragma unroll
            for (int q = 0; q < 4; q++) {
                float4 xv = x4[(size_t)nn[i] * (IN_DIM / 4) + d0 / 4 + q];
                float s0, s1, s2, s3;
                unpack2(acc[i][2 * q], s0, s1);
                unpack2(acc[i][2 * q + 1], s2, s3);
                float4 r;
                r.x = s0 + xv.x; r.y = s1 + xv.y; r.z = s2 + xv.z; r.w = s3 + xv.w;
                o4[(size_t)nn[i] * (IN_DIM / 4) + d0 / 4 + q] = r;
            }
        }
    }
}

// ---------------------------------------------------------------------------
extern "C" void kernel_launch(void* const* d_in, const int* in_sizes, int n_in,
                              void* d_out, int out_size) {
    const float* x     = (const float*)d_in[0];
    const int*   ei    = (const int*)d_in[1];   // jax canonicalizes int64 -> int32
    const float* W_sim = (const float*)d_in[2];
    const float* b_sim = (const float*)d_in[3];
    const float* w_vec = (const float*)d_in[4];
    const float* b_vec = (const float*)d_in[5];
    const float* W1    = (const float*)d_in[6];
    const float* b1    = (const float*)d_in[7];
    const float* W2    = (const float*)d_in[8];
    const float* b2    = (const float*)d_in[9];
    float* out = (float*)d_out;

    int N = in_sizes[0] / IN_DIM;
    long long E = (long long)in_sizes[1] / 2;
    int nblk = (N + TN - 1) / TN;

    // zero accumulator + compute gates (independent)
    size_t n4 = (size_t)N * IN_DIM / 4;
    zero_kernel<<<(unsigned)((n4 + 255) / 256), 256>>>(n4);
    gate_kernel<<<nblk, 256>>>(x, W_sim, b_sim, w_vec, b_vec, N);

    // scatter: one warp per edge, 8 warps per block
    int wpb = 256 / 32;
    scatter_kernel<<<(unsigned)((E + wpb - 1) / wpb), 256>>>(x, ei, E);

    // fused MLP + residual (dynamic smem: W1+W2+hT+biases)
    int smem_bytes = (8192 + 8192 + HIDDEN * HT_PAD + HIDDEN + IN_DIM) * sizeof(float);
    cudaFuncSetAttribute(mlp_kernel, cudaFuncAttributeMaxDynamicSharedMemorySize, smem_bytes);
    mlp_kernel<<<nblk, 256, smem_bytes>>>(x, W1, b1, W2, b2, out, N);
}

// round 4
// speedup vs baseline: 1.5069x; 1.5069x over previous
#include <cuda_runtime.h>

#define N_NODES 100000
#define IN_DIM 128
#define HIDDEN 64
#define TN 128          // nodes per block tile
#define TNP (TN + 1)    // padded tile row, in float4 units
#define HTP (TN + 4)    // padded hT row, in floats

// Scratch (allocation-guard-safe: __device__ globals)
__device__ float g_weights[N_NODES];
__device__ float g_readout[(size_t)N_NODES * IN_DIM];

// ---------------------------------------------------------------------------
// Packed f32x2 helpers (sm_103a)
// ---------------------------------------------------------------------------
__device__ __forceinline__ unsigned long long pack2(float a, float b) {
    unsigned long long r;
    asm("mov.b64 %0, {%1, %2};" : "=l"(r) : "f"(a), "f"(b));
    return r;
}
__device__ __forceinline__ void fma2(unsigned long long& d,
                                     unsigned long long a,
                                     unsigned long long b) {
    asm("fma.rn.f32x2 %0, %1, %2, %0;" : "+l"(d) : "l"(a), "l"(b));
}
__device__ __forceinline__ void unpack2(unsigned long long v, float& lo, float& hi) {
    asm("mov.b64 {%0, %1}, %2;" : "=f"(lo), "=f"(hi) : "l"(v));
}
__device__ __forceinline__ float tanh_fast(float x) {
    float y;
    asm("tanh.approx.f32 %0, %1;" : "=f"(y) : "f"(x));
    return y;
}

// ---------------------------------------------------------------------------
// Kernel 1: gate + zero-readout.
// smem layout (floats): Ws[8192] | tile4[32*TNP (float4)] | bs[64] | wv[64] | part[8*128]
// ---------------------------------------------------------------------------
__global__ void __launch_bounds__(256)
gate_kernel(const float* __restrict__ x,
            const float* __restrict__ W_sim,
            const float* __restrict__ b_sim,
            const float* __restrict__ w_vec,
            const float* __restrict__ b_vec,
            int N) {
    extern __shared__ __align__(16) float smem[];
    float*  Ws    = smem;                          // 8192
    float4* tile4 = (float4*)(smem + 8192);        // 32*TNP float4 = 16512 floats
    float*  bs    = smem + 8192 + 32 * TNP * 4;    // 64
    float*  wv    = bs + HIDDEN;                   // 64
    float*  part  = wv + HIDDEN;                   // 8*128

    const int tx   = threadIdx.x & 31;
    const int ty   = threadIdx.x >> 5;
    const int base = blockIdx.x * TN;

    // zero this block's slice of g_readout (must finish before scatter kernel; stream order guarantees it)
    {
        float4* ro4 = reinterpret_cast<float4*>(g_readout);
        size_t r0 = (size_t)base * (IN_DIM / 4);
        int limit4 = min(TN, N - base) * (IN_DIM / 4);
        float4 z = make_float4(0.f, 0.f, 0.f, 0.f);
        for (int i = threadIdx.x; i < limit4; i += 256) ro4[r0 + i] = z;
    }

    for (int i = threadIdx.x; i < IN_DIM * HIDDEN; i += 256) Ws[i] = W_sim[i];
    if (threadIdx.x < HIDDEN) { bs[threadIdx.x] = b_sim[threadIdx.x]; wv[threadIdx.x] = w_vec[threadIdx.x]; }

    // stage x tile: warp per node-row, lane = k4 (coalesced); store [k4][node] (conflict-free w/ pad)
    {
        const float4* x4 = reinterpret_cast<const float4*>(x);
        float4 z = make_float4(0.f, 0.f, 0.f, 0.f);
#pragma unroll
        for (int it = 0; it < 16; it++) {
            int node = ty + 8 * it;
            int n = base + node;
            float4 v = (n < N) ? x4[(size_t)n * (IN_DIM / 4) + tx] : z;
            tile4[tx * TNP + node] = v;
        }
    }
    __syncthreads();

    const int h0 = ty * 8;
    unsigned long long acc[4][4];
    {
        ulonglong2 b01 = *reinterpret_cast<const ulonglong2*>(&bs[h0]);
        ulonglong2 b23 = *reinterpret_cast<const ulonglong2*>(&bs[h0 + 4]);
#pragma unroll
        for (int i = 0; i < 4; i++) {
            acc[i][0] = b01.x; acc[i][1] = b01.y; acc[i][2] = b23.x; acc[i][3] = b23.y;
        }
    }

#pragma unroll 4
    for (int k4 = 0; k4 < IN_DIM / 4; k4++) {
        float4 a[4];
#pragma unroll
        for (int i = 0; i < 4; i++) a[i] = tile4[k4 * TNP + tx + 32 * i];
#pragma unroll
        for (int kk = 0; kk < 4; kk++) {
            const float* wr = Ws + (k4 * 4 + kk) * HIDDEN + h0;
            ulonglong2 w01 = *reinterpret_cast<const ulonglong2*>(wr);
            ulonglong2 w23 = *reinterpret_cast<const ulonglong2*>(wr + 4);
#pragma unroll
            for (int i = 0; i < 4; i++) {
                float xv = (kk == 0) ? a[i].x : (kk == 1) ? a[i].y : (kk == 2) ? a[i].z : a[i].w;
                unsigned long long xp = pack2(xv, xv);
                fma2(acc[i][0], xp, w01.x);
                fma2(acc[i][1], xp, w01.y);
                fma2(acc[i][2], xp, w23.x);
                fma2(acc[i][3], xp, w23.y);
            }
        }
    }

    // tanh + dot with w_vec over this thread's 8 hidden dims
    float p[4] = {0.f, 0.f, 0.f, 0.f};
#pragma unroll
    for (int j = 0; j < 4; j++) {
        float wlo = wv[h0 + 2 * j], whi = wv[h0 + 2 * j + 1];
#pragma unroll
        for (int i = 0; i < 4; i++) {
            float t0, t1;
            unpack2(acc[i][j], t0, t1);
            p[i] = fmaf(tanh_fast(t0), wlo, p[i]);
            p[i] = fmaf(tanh_fast(t1), whi, p[i]);
        }
    }
#pragma unroll
    for (int i = 0; i < 4; i++) part[ty * TN + tx + 32 * i] = p[i];
    __syncthreads();

    if (threadIdx.x < TN) {
        int n = base + threadIdx.x;
        if (n < N) {
            float s = b_vec[0];
#pragma unroll
            for (int r = 0; r < 8; r++) s += part[r * TN + threadIdx.x];
            g_weights[n] = 1.0f / (1.0f + expf(-s));
        }
    }
}

// ---------------------------------------------------------------------------
// Kernel 2: scatter  readout[row] += x[col] * weights[col]   (warp per edge)
// ---------------------------------------------------------------------------
__device__ __forceinline__ void red_add_v4(float* addr, float4 v) {
    asm volatile("red.global.add.v4.f32 [%0], {%1,%2,%3,%4};"
                 :: "l"(addr), "f"(v.x), "f"(v.y), "f"(v.z), "f"(v.w)
                 : "memory");
}

__global__ void __launch_bounds__(256)
scatter_kernel(const float* __restrict__ x,
               const int* __restrict__ ei,   // [2, E] int32
               long long E) {
    long long w = (long long)blockIdx.x * (blockDim.x >> 5) + (threadIdx.x >> 5);
    if (w >= E) return;
    int lane = threadIdx.x & 31;
    int row = ei[w];        // destination
    int col = ei[E + w];    // source
    float g = g_weights[col];
    float4 v = reinterpret_cast<const float4*>(x)[(size_t)col * (IN_DIM / 4) + lane];
    v.x *= g; v.y *= g; v.z *= g; v.w *= g;
    float* dst = g_readout + (size_t)row * IN_DIM + lane * 4;
    red_add_v4(dst, v);
}

// ---------------------------------------------------------------------------
// Kernel 3: out = x + relu(readout@W1+b1)@W2 + b2
// smem (floats): Wbuf[8192] | tile region [32*TNP float4 = 16512] | b1s[64] | b2s[128]
// tile region reused: readout tile -> hT -> out staging
// ---------------------------------------------------------------------------
__global__ void __launch_bounds__(256)
mlp_kernel(const float* __restrict__ x,
           const float* __restrict__ W1,
           const float* __restrict__ b1,
           const float* __restrict__ W2,
           const float* __restrict__ b2,
           float* __restrict__ out, int N) {
    extern __shared__ __align__(16) float smem[];
    float*  Wbuf  = smem;                          // 8192 floats (W1, then W2)
    float4* tile4 = (float4*)(smem + 8192);        // 32*TNP float4
    float*  hT    = smem + 8192;                   // same region as floats: 64*HTP = 8448 <= 16512
    float*  b1s   = smem + 8192 + 32 * TNP * 4;    // 64
    float*  b2s   = b1s + HIDDEN;                  // 128

    const int tx   = threadIdx.x & 31;
    const int ty   = threadIdx.x >> 5;
    const int base = blockIdx.x * TN;

    for (int i = threadIdx.x; i < IN_DIM * HIDDEN; i += 256) Wbuf[i] = W1[i];
    if (threadIdx.x < HIDDEN) b1s[threadIdx.x] = b1[threadIdx.x];
    if (threadIdx.x < IN_DIM) b2s[threadIdx.x] = b2[threadIdx.x];

    // stage readout tile (coalesced, conflict-free)
    {
        const float4* r4 = reinterpret_cast<const float4*>(g_readout);
        float4 z = make_float4(0.f, 0.f, 0.f, 0.f);
#pragma unroll
        for (int it = 0; it < 16; it++) {
            int node = ty + 8 * it;
            int n = base + node;
            float4 v = (n < N) ? r4[(size_t)n * (IN_DIM / 4) + tx] : z;
            tile4[tx * TNP + node] = v;
        }
    }
    __syncthreads();

    // ---- stage 1: h = relu(readout @ W1 + b1), thread = 4 nodes x 8 hidden ----
    unsigned long long acc1[4][4];
    {
        const int h0 = ty * 8;
        ulonglong2 b01 = *reinterpret_cast<const ulonglong2*>(&b1s[h0]);
        ulonglong2 b23 = *reinterpret_cast<const ulonglong2*>(&b1s[h0 + 4]);
#pragma unroll
        for (int i = 0; i < 4; i++) {
            acc1[i][0] = b01.x; acc1[i][1] = b01.y; acc1[i][2] = b23.x; acc1[i][3] = b23.y;
        }

#pragma unroll 4
        for (int k4 = 0; k4 < IN_DIM / 4; k4++) {
            float4 a[4];
#pragma unroll
            for (int i = 0; i < 4; i++) a[i] = tile4[k4 * TNP + tx + 32 * i];
#pragma unroll
            for (int kk = 0; kk < 4; kk++) {
                const float* wr = Wbuf + (k4 * 4 + kk) * HIDDEN + h0;
                ulonglong2 w01 = *reinterpret_cast<const ulonglong2*>(wr);
                ulonglong2 w23 = *reinterpret_cast<const ulonglong2*>(wr + 4);
#pragma unroll
                for (int i = 0; i < 4; i++) {
                    float xv = (kk == 0) ? a[i].x : (kk == 1) ? a[i].y : (kk == 2) ? a[i].z : a[i].w;
                    unsigned long long xp = pack2(xv, xv);
                    fma2(acc1[i][0], xp, w01.x);
                    fma2(acc1[i][1], xp, w01.y);
                    fma2(acc1[i][2], xp, w23.x);
                    fma2(acc1[i][3], xp, w23.y);
                }
            }
        }
    }
    __syncthreads();   // everyone done reading tile + Wbuf(W1)

    // write hT (relu) into tile region; concurrently reload Wbuf <- W2
    {
        const int h0 = ty * 8;
#pragma unroll
        for (int j = 0; j < 4; j++) {
#pragma unroll
            for (int i = 0; i < 4; i++) {
                float t0, t1;
                unpack2(acc1[i][j], t0, t1);
                hT[(h0 + 2 * j)     * HTP + tx + 32 * i] = fmaxf(t0, 0.f);
                hT[(h0 + 2 * j + 1) * HTP + tx + 32 * i] = fmaxf(t1, 0.f);
            }
        }
    }
    for (int i = threadIdx.x; i < HIDDEN * IN_DIM; i += 256) Wbuf[i] = W2[i];
    __syncthreads();

    // ---- stage 2: acc = h @ W2 + b2, thread = 4 nodes x 16 out dims ----
    const int d0 = ty * 16;
    unsigned long long acc[4][8];
    {
        const ulonglong2* bp = reinterpret_cast<const ulonglong2*>(&b2s[d0]);
#pragma unroll
        for (int q = 0; q < 4; q++) {
            ulonglong2 b = bp[q];
#pragma unroll
            for (int i = 0; i < 4; i++) { acc[i][2 * q] = b.x; acc[i][2 * q + 1] = b.y; }
        }
    }

#pragma unroll 4
    for (int k = 0; k < HIDDEN; k++) {
        float hv[4];
#pragma unroll
        for (int i = 0; i < 4; i++) hv[i] = hT[k * HTP + tx + 32 * i];
        const ulonglong2* wp = reinterpret_cast<const ulonglong2*>(Wbuf + k * IN_DIM + d0);
        ulonglong2 w0 = wp[0], w1 = wp[1], w2 = wp[2], w3 = wp[3];
#pragma unroll
        for (int i = 0; i < 4; i++) {
            unsigned long long xp = pack2(hv[i], hv[i]);
            fma2(acc[i][0], xp, w0.x); fma2(acc[i][1], xp, w0.y);
            fma2(acc[i][2], xp, w1.x); fma2(acc[i][3], xp, w1.y);
            fma2(acc[i][4], xp, w2.x); fma2(acc[i][5], xp, w2.y);
            fma2(acc[i][6], xp, w3.x); fma2(acc[i][7], xp, w3.y);
        }
    }
    __syncthreads();   // done reading hT; tile region free for out staging

    // stage out into tile region: [d4][node], conflict-free
#pragma unroll
    for (int q = 0; q < 4; q++) {
#pragma unroll
        for (int i = 0; i < 4; i++) {
            float s0, s1, s2, s3;
            unpack2(acc[i][2 * q], s0, s1);
            unpack2(acc[i][2 * q + 1], s2, s3);
            tile4[(d0 / 4 + q) * TNP + tx + 32 * i] = make_float4(s0, s1, s2, s3);
        }
    }
    __syncthreads();

    // coalesced epilogue: out = staged + x
    {
        const float4* x4 = reinterpret_cast<const float4*>(x);
        float4* o4 = reinterpret_cast<float4*>(out);
#pragma unroll
        for (int it = 0; it < 16; it++) {
            int node = ty + 8 * it;
            int n = base + node;
            if (n < N) {
                float4 s = tile4[tx * TNP + node];
                float4 xv = x4[(size_t)n * (IN_DIM / 4) + tx];
                s.x += xv.x; s.y += xv.y; s.z += xv.z; s.w += xv.w;
                o4[(size_t)n * (IN_DIM / 4) + tx] = s;
            }
        }
    }
}

// ---------------------------------------------------------------------------
extern "C" void kernel_launch(void* const* d_in, const int* in_sizes, int n_in,
                              void* d_out, int out_size) {
    const float* x     = (const float*)d_in[0];
    const int*   ei    = (const int*)d_in[1];   // jax canonicalizes int64 -> int32
    const float* W_sim = (const float*)d_in[2];
    const float* b_sim = (const float*)d_in[3];
    const float* w_vec = (const float*)d_in[4];
    const float* b_vec = (const float*)d_in[5];
    const float* W1    = (const float*)d_in[6];
    const float* b1    = (const float*)d_in[7];
    const float* W2    = (const float*)d_in[8];
    const float* b2    = (const float*)d_in[9];
    float* out = (float*)d_out;

    int N = in_sizes[0] / IN_DIM;
    long long E = (long long)in_sizes[1] / 2;
    int nblk = (N + TN - 1) / TN;

    int gate_smem = (8192 + 32 * TNP * 4 + HIDDEN + HIDDEN + 8 * TN) * (int)sizeof(float);
    cudaFuncSetAttribute(gate_kernel, cudaFuncAttributeMaxDynamicSharedMemorySize, gate_smem);
    gate_kernel<<<nblk, 256, gate_smem>>>(x, W_sim, b_sim, w_vec, b_vec, N);

    // scatter: one warp per edge, 8 warps per block
    int wpb = 256 / 32;
    scatter_kernel<<<(unsigned)((E + wpb - 1) / wpb), 256>>>(x, ei, E);

    int mlp_smem = (8192 + 32 * TNP * 4 + HIDDEN + IN_DIM) * (int)sizeof(float);
    cudaFuncSetAttribute(mlp_kernel, cudaFuncAttributeMaxDynamicSharedMemorySize, mlp_smem);
    mlp_kernel<<<nblk, 256, mlp_smem>>>(x, W1, b1, W2, b2, out, N);
}

// round 5
// speedup vs baseline: 1.9959x; 1.3245x over previous
#include <cuda_runtime.h>

#define N_NODES 100000
#define MAX_E   1600000
#define IN_DIM 128
#define HIDDEN 64
#define TN 128          // nodes per block tile
#define TNP (TN + 1)    // padded tile row, in float4 units
#define HTP (TN + 4)    // padded hT row, in floats
#define SCAN_CHUNK 1024

// Scratch (allocation-guard-safe: __device__ globals)
__device__ float g_weights[N_NODES];
__device__ int   g_cnt[N_NODES];
__device__ int   g_off[N_NODES + 1];
__device__ int   g_cur[N_NODES];
__device__ int   g_bsum[128];
__device__ int   g_scol[MAX_E];

// ---------------------------------------------------------------------------
// Packed f32x2 helpers (sm_103a)
// ---------------------------------------------------------------------------
__device__ __forceinline__ unsigned long long pack2(float a, float b) {
    unsigned long long r;
    asm("mov.b64 %0, {%1, %2};" : "=l"(r) : "f"(a), "f"(b));
    return r;
}
__device__ __forceinline__ void fma2(unsigned long long& d,
                                     unsigned long long a,
                                     unsigned long long b) {
    asm("fma.rn.f32x2 %0, %1, %2, %0;" : "+l"(d) : "l"(a), "l"(b));
}
__device__ __forceinline__ void unpack2(unsigned long long v, float& lo, float& hi) {
    asm("mov.b64 {%0, %1}, %2;" : "=f"(lo), "=f"(hi) : "l"(v));
}
__device__ __forceinline__ float tanh_fast(float x) {
    float y;
    asm("tanh.approx.f32 %0, %1;" : "=f"(y) : "f"(x));
    return y;
}

// ---------------------------------------------------------------------------
// CSR build: zero -> hist -> scanA -> scanB -> scanC -> reorder
// ---------------------------------------------------------------------------
__global__ void kzero(int N) {
    int i = blockIdx.x * blockDim.x + threadIdx.x;
    if (i < N) g_cnt[i] = 0;
}

__global__ void khist(const int* __restrict__ ei, int E) {
    int e = blockIdx.x * blockDim.x + threadIdx.x;
    if (e < E) atomicAdd(&g_cnt[ei[e]], 1);
}

__global__ void __launch_bounds__(256)
kscanA(int N) {
    int b = blockIdx.x, tid = threadIdx.x;
    int base = b * SCAN_CHUNK + tid * 4;
    int4 v = make_int4(0, 0, 0, 0);
    if (base + 3 < N) v = *reinterpret_cast<const int4*>(&g_cnt[base]);
    else {
        if (base + 0 < N) v.x = g_cnt[base + 0];
        if (base + 1 < N) v.y = g_cnt[base + 1];
        if (base + 2 < N) v.z = g_cnt[base + 2];
        if (base + 3 < N) v.w = g_cnt[base + 3];
    }
    int s = v.x + v.y + v.z + v.w;

    // block exclusive scan of s over 256 threads
    int lane = tid & 31, w = tid >> 5;
    int x = s;
#pragma unroll
    for (int o = 1; o < 32; o <<= 1) {
        int y = __shfl_up_sync(0xffffffffu, x, o);
        if (lane >= o) x += y;
    }
    __shared__ int wt[8];
    if (lane == 31) wt[w] = x;
    __syncthreads();
    if (tid == 0) {
        int run = 0;
#pragma unroll
        for (int i = 0; i < 8; i++) { int t = wt[i]; wt[i] = run; run += t; }
    }
    __syncthreads();
    int excl = x - s + wt[w];

    int r = excl;
    if (base + 0 < N) { g_off[base + 0] = r; r += v.x; }
    if (base + 1 < N) { g_off[base + 1] = r; r += v.y; }
    if (base + 2 < N) { g_off[base + 2] = r; r += v.z; }
    if (base + 3 < N) { g_off[base + 3] = r; r += v.w; }

    if (tid == 255) g_bsum[b] = excl + s;
}

__global__ void kscanB(int nb) {
    __shared__ int sm[128];
    int tid = threadIdx.x;
    if (tid < nb) sm[tid] = g_bsum[tid];
    __syncthreads();
    if (tid == 0) {
        int run = 0;
        for (int i = 0; i < nb; i++) { int t = sm[i]; sm[i] = run; run += t; }
    }
    __syncthreads();
    if (tid < nb) g_bsum[tid] = sm[tid];
}

__global__ void kscanC(int N, int E) {
    int i = blockIdx.x * blockDim.x + threadIdx.x;
    if (i < N) {
        int o = g_off[i] + g_bsum[i >> 10];
        g_off[i] = o;
        g_cur[i] = o;
    }
    if (i == 0) g_off[N] = E;
}

__global__ void kreorder(const int* __restrict__ ei, int E) {
    int e = blockIdx.x * blockDim.x + threadIdx.x;
    if (e < E) {
        int r = ei[e];
        int c = ei[E + e];
        int p = atomicAdd(&g_cur[r], 1);
        g_scol[p] = c;
    }
}

// ---------------------------------------------------------------------------
// Gate kernel (round-4 structure, readout-zeroing removed)
// smem (floats): Ws[8192] | tile4[32*TNP f4] | bs[64] | wv[64] | part[8*128]
// ---------------------------------------------------------------------------
__global__ void __launch_bounds__(256)
gate_kernel(const float* __restrict__ x,
            const float* __restrict__ W_sim,
            const float* __restrict__ b_sim,
            const float* __restrict__ w_vec,
            const float* __restrict__ b_vec,
            int N) {
    extern __shared__ __align__(16) float smem[];
    float*  Ws    = smem;
    float4* tile4 = (float4*)(smem + 8192);
    float*  bs    = smem + 8192 + 32 * TNP * 4;
    float*  wv    = bs + HIDDEN;
    float*  part  = wv + HIDDEN;

    const int tx   = threadIdx.x & 31;
    const int ty   = threadIdx.x >> 5;
    const int base = blockIdx.x * TN;

    for (int i = threadIdx.x; i < IN_DIM * HIDDEN; i += 256) Ws[i] = W_sim[i];
    if (threadIdx.x < HIDDEN) { bs[threadIdx.x] = b_sim[threadIdx.x]; wv[threadIdx.x] = w_vec[threadIdx.x]; }

    {
        const float4* x4 = reinterpret_cast<const float4*>(x);
        float4 z = make_float4(0.f, 0.f, 0.f, 0.f);
#pragma unroll
        for (int it = 0; it < 16; it++) {
            int node = ty + 8 * it;
            int n = base + node;
            float4 v = (n < N) ? x4[(size_t)n * (IN_DIM / 4) + tx] : z;
            tile4[tx * TNP + node] = v;
        }
    }
    __syncthreads();

    const int h0 = ty * 8;
    unsigned long long acc[4][4];
    {
        ulonglong2 b01 = *reinterpret_cast<const ulonglong2*>(&bs[h0]);
        ulonglong2 b23 = *reinterpret_cast<const ulonglong2*>(&bs[h0 + 4]);
#pragma unroll
        for (int i = 0; i < 4; i++) {
            acc[i][0] = b01.x; acc[i][1] = b01.y; acc[i][2] = b23.x; acc[i][3] = b23.y;
        }
    }

#pragma unroll 4
    for (int k4 = 0; k4 < IN_DIM / 4; k4++) {
        float4 a[4];
#pragma unroll
        for (int i = 0; i < 4; i++) a[i] = tile4[k4 * TNP + tx + 32 * i];
#pragma unroll
        for (int kk = 0; kk < 4; kk++) {
            const float* wr = Ws + (k4 * 4 + kk) * HIDDEN + h0;
            ulonglong2 w01 = *reinterpret_cast<const ulonglong2*>(wr);
            ulonglong2 w23 = *reinterpret_cast<const ulonglong2*>(wr + 4);
#pragma unroll
            for (int i = 0; i < 4; i++) {
                float xv = (kk == 0) ? a[i].x : (kk == 1) ? a[i].y : (kk == 2) ? a[i].z : a[i].w;
                unsigned long long xp = pack2(xv, xv);
                fma2(acc[i][0], xp, w01.x);
                fma2(acc[i][1], xp, w01.y);
                fma2(acc[i][2], xp, w23.x);
                fma2(acc[i][3], xp, w23.y);
            }
        }
    }

    float p[4] = {0.f, 0.f, 0.f, 0.f};
#pragma unroll
    for (int j = 0; j < 4; j++) {
        float wlo = wv[h0 + 2 * j], whi = wv[h0 + 2 * j + 1];
#pragma unroll
        for (int i = 0; i < 4; i++) {
            float t0, t1;
            unpack2(acc[i][j], t0, t1);
            p[i] = fmaf(tanh_fast(t0), wlo, p[i]);
            p[i] = fmaf(tanh_fast(t1), whi, p[i]);
        }
    }
#pragma unroll
    for (int i = 0; i < 4; i++) part[ty * TN + tx + 32 * i] = p[i];
    __syncthreads();

    if (threadIdx.x < TN) {
        int n = base + threadIdx.x;
        if (n < N) {
            float s = b_vec[0];
#pragma unroll
            for (int r = 0; r < 8; r++) s += part[r * TN + threadIdx.x];
            g_weights[n] = 1.0f / (1.0f + expf(-s));
        }
    }
}

// ---------------------------------------------------------------------------
// Fused kernel: CSR gather-accumulate (registers, no atomics) -> MLP -> out
// smem (floats): Wbuf[8192] | tile region [32*TNP f4] | b1s[64] | b2s[128]
// ---------------------------------------------------------------------------
__global__ void __launch_bounds__(256)
fused_kernel(const float* __restrict__ x,
             const float* __restrict__ W1,
             const float* __restrict__ b1,
             const float* __restrict__ W2,
             const float* __restrict__ b2,
             float* __restrict__ out, int N) {
    extern __shared__ __align__(16) float smem[];
    float*  Wbuf  = smem;                          // W1 then W2
    float4* tile4 = (float4*)(smem + 8192);
    float*  hT    = smem + 8192;
    float*  b1s   = smem + 8192 + 32 * TNP * 4;
    float*  b2s   = b1s + HIDDEN;

    const int tx   = threadIdx.x & 31;
    const int ty   = threadIdx.x >> 5;
    const int base = blockIdx.x * TN;

    for (int i = threadIdx.x; i < IN_DIM * HIDDEN; i += 256) Wbuf[i] = W1[i];
    if (threadIdx.x < HIDDEN) b1s[threadIdx.x] = b1[threadIdx.x];
    if (threadIdx.x < IN_DIM) b2s[threadIdx.x] = b2[threadIdx.x];

    // ---- gather: warp accumulates its node's row in registers (no atomics) ----
    {
        const float4* x4 = reinterpret_cast<const float4*>(x);
#pragma unroll
        for (int it = 0; it < 16; it++) {
            int node = ty + 8 * it;
            int n = base + node;
            float4 a0 = make_float4(0.f, 0.f, 0.f, 0.f);
            float4 a1 = make_float4(0.f, 0.f, 0.f, 0.f);
            if (n < N) {
                int s  = g_off[n];
                int e2 = g_off[n + 1];
                int j = s;
                for (; j + 1 < e2; j += 2) {
                    int c0 = g_scol[j], c1 = g_scol[j + 1];
                    float w0 = g_weights[c0], w1 = g_weights[c1];
                    float4 v0 = x4[(size_t)c0 * (IN_DIM / 4) + tx];
                    float4 v1 = x4[(size_t)c1 * (IN_DIM / 4) + tx];
                    a0.x = fmaf(w0, v0.x, a0.x); a0.y = fmaf(w0, v0.y, a0.y);
                    a0.z = fmaf(w0, v0.z, a0.z); a0.w = fmaf(w0, v0.w, a0.w);
                    a1.x = fmaf(w1, v1.x, a1.x); a1.y = fmaf(w1, v1.y, a1.y);
                    a1.z = fmaf(w1, v1.z, a1.z); a1.w = fmaf(w1, v1.w, a1.w);
                }
                if (j < e2) {
                    int c0 = g_scol[j];
                    float w0 = g_weights[c0];
                    float4 v0 = x4[(size_t)c0 * (IN_DIM / 4) + tx];
                    a0.x = fmaf(w0, v0.x, a0.x); a0.y = fmaf(w0, v0.y, a0.y);
                    a0.z = fmaf(w0, v0.z, a0.z); a0.w = fmaf(w0, v0.w, a0.w);
                }
            }
            a0.x += a1.x; a0.y += a1.y; a0.z += a1.z; a0.w += a1.w;
            tile4[tx * TNP + node] = a0;
        }
    }
    __syncthreads();

    // ---- stage 1: h = relu(readout @ W1 + b1), thread = 4 nodes x 8 hidden ----
    unsigned long long acc1[4][4];
    {
        const int h0 = ty * 8;
        ulonglong2 b01 = *reinterpret_cast<const ulonglong2*>(&b1s[h0]);
        ulonglong2 b23 = *reinterpret_cast<const ulonglong2*>(&b1s[h0 + 4]);
#pragma unroll
        for (int i = 0; i < 4; i++) {
            acc1[i][0] = b01.x; acc1[i][1] = b01.y; acc1[i][2] = b23.x; acc1[i][3] = b23.y;
        }

#pragma unroll 4
        for (int k4 = 0; k4 < IN_DIM / 4; k4++) {
            float4 a[4];
#pragma unroll
            for (int i = 0; i < 4; i++) a[i] = tile4[k4 * TNP + tx + 32 * i];
#pragma unroll
            for (int kk = 0; kk < 4; kk++) {
                const float* wr = Wbuf + (k4 * 4 + kk) * HIDDEN + h0;
                ulonglong2 w01 = *reinterpret_cast<const ulonglong2*>(wr);
                ulonglong2 w23 = *reinterpret_cast<const ulonglong2*>(wr + 4);
#pragma unroll
                for (int i = 0; i < 4; i++) {
                    float xv = (kk == 0) ? a[i].x : (kk == 1) ? a[i].y : (kk == 2) ? a[i].z : a[i].w;
                    unsigned long long xp = pack2(xv, xv);
                    fma2(acc1[i][0], xp, w01.x);
                    fma2(acc1[i][1], xp, w01.y);
                    fma2(acc1[i][2], xp, w23.x);
                    fma2(acc1[i][3], xp, w23.y);
                }
            }
        }
    }
    __syncthreads();

    // relu -> hT (tile region); reload Wbuf <- W2
    {
        const int h0 = ty * 8;
#pragma unroll
        for (int j = 0; j < 4; j++) {
#pragma unroll
            for (int i = 0; i < 4; i++) {
                float t0, t1;
                unpack2(acc1[i][j], t0, t1);
                hT[(h0 + 2 * j)     * HTP + tx + 32 * i] = fmaxf(t0, 0.f);
                hT[(h0 + 2 * j + 1) * HTP + tx + 32 * i] = fmaxf(t1, 0.f);
            }
        }
    }
    for (int i = threadIdx.x; i < HIDDEN * IN_DIM; i += 256) Wbuf[i] = W2[i];
    __syncthreads();

    // ---- stage 2: acc = h @ W2 + b2, thread = 4 nodes x 16 out dims ----
    const int d0 = ty * 16;
    unsigned long long acc[4][8];
    {
        const ulonglong2* bp = reinterpret_cast<const ulonglong2*>(&b2s[d0]);
#pragma unroll
        for (int q = 0; q < 4; q++) {
            ulonglong2 b = bp[q];
#pragma unroll
            for (int i = 0; i < 4; i++) { acc[i][2 * q] = b.x; acc[i][2 * q + 1] = b.y; }
        }
    }

#pragma unroll 4
    for (int k = 0; k < HIDDEN; k++) {
        float hv[4];
#pragma unroll
        for (int i = 0; i < 4; i++) hv[i] = hT[k * HTP + tx + 32 * i];
        const ulonglong2* wp = reinterpret_cast<const ulonglong2*>(Wbuf + k * IN_DIM + d0);
        ulonglong2 w0 = wp[0], w1 = wp[1], w2 = wp[2], w3 = wp[3];
#pragma unroll
        for (int i = 0; i < 4; i++) {
            unsigned long long xp = pack2(hv[i], hv[i]);
            fma2(acc[i][0], xp, w0.x); fma2(acc[i][1], xp, w0.y);
            fma2(acc[i][2], xp, w1.x); fma2(acc[i][3], xp, w1.y);
            fma2(acc[i][4], xp, w2.x); fma2(acc[i][5], xp, w2.y);
            fma2(acc[i][6], xp, w3.x); fma2(acc[i][7], xp, w3.y);
        }
    }
    __syncthreads();

    // stage out into tile region, then coalesced epilogue out = staged + x
#pragma unroll
    for (int q = 0; q < 4; q++) {
#pragma unroll
        for (int i = 0; i < 4; i++) {
            float s0, s1, s2, s3;
            unpack2(acc[i][2 * q], s0, s1);
            unpack2(acc[i][2 * q + 1], s2, s3);
            tile4[(d0 / 4 + q) * TNP + tx + 32 * i] = make_float4(s0, s1, s2, s3);
        }
    }
    __syncthreads();

    {
        const float4* x4 = reinterpret_cast<const float4*>(x);
        float4* o4 = reinterpret_cast<float4*>(out);
#pragma unroll
        for (int it = 0; it < 16; it++) {
            int node = ty + 8 * it;
            int n = base + node;
            if (n < N) {
                float4 s = tile4[tx * TNP + node];
                float4 xv = x4[(size_t)n * (IN_DIM / 4) + tx];
                s.x += xv.x; s.y += xv.y; s.z += xv.z; s.w += xv.w;
                o4[(size_t)n * (IN_DIM / 4) + tx] = s;
            }
        }
    }
}

// ---------------------------------------------------------------------------
extern "C" void kernel_launch(void* const* d_in, const int* in_sizes, int n_in,
                              void* d_out, int out_size) {
    const float* x     = (const float*)d_in[0];
    const int*   ei    = (const int*)d_in[1];   // jax canonicalizes int64 -> int32
    const float* W_sim = (const float*)d_in[2];
    const float* b_sim = (const float*)d_in[3];
    const float* w_vec = (const float*)d_in[4];
    const float* b_vec = (const float*)d_in[5];
    const float* W1    = (const float*)d_in[6];
    const float* b1    = (const float*)d_in[7];
    const float* W2    = (const float*)d_in[8];
    const float* b2    = (const float*)d_in[9];
    float* out = (float*)d_out;

    int N = in_sizes[0] / IN_DIM;
    int E = in_sizes[1] / 2;
    int nblk = (N + TN - 1) / TN;
    int nscan = (N + SCAN_CHUNK - 1) / SCAN_CHUNK;

    // gate (independent of CSR build)
    int gate_smem = (8192 + 32 * TNP * 4 + HIDDEN + HIDDEN + 8 * TN) * (int)sizeof(float);
    cudaFuncSetAttribute(gate_kernel, cudaFuncAttributeMaxDynamicSharedMemorySize, gate_smem);
    gate_kernel<<<nblk, 256, gate_smem>>>(x, W_sim, b_sim, w_vec, b_vec, N);

    // CSR build
    kzero<<<(N + 255) / 256, 256>>>(N);
    khist<<<(E + 255) / 256, 256>>>(ei, E);
    kscanA<<<nscan, 256>>>(N);
    kscanB<<<1, 128>>>(nscan);
    kscanC<<<(N + 255) / 256, 256>>>(N, E);
    kreorder<<<(E + 255) / 256, 256>>>(ei, E);

    // fused gather + MLP + residual
    int fused_smem = (8192 + 32 * TNP * 4 + HIDDEN + IN_DIM) * (int)sizeof(float);
    cudaFuncSetAttribute(fused_kernel, cudaFuncAttributeMaxDynamicSharedMemorySize, fused_smem);
    fused_kernel<<<nblk, 256, fused_smem>>>(x, W1, b1, W2, b2, out, N);
}